// round 1
// baseline (speedup 1.0000x reference)
#include <cuda_runtime.h>

#define BB 256
#define TT 2048
#define VV 128
#define CC 512
#define KK 10

// scratch (no device allocs allowed)
__device__ float g_alpha[BB * KK];
__device__ float g_beta[BB * KK];
__device__ float g_kappa[BB * KK];

// -------- Kernel 1: params GEMM (B x 30 over C=512), kappa, zero w --------
__global__ void k_params(const float* __restrict__ x,
                         const float* __restrict__ kap_old,
                         const float* __restrict__ W,
                         const float* __restrict__ bias,
                         float* __restrict__ out_w,
                         float* __restrict__ out_kappa) {
    __shared__ float xs[CC];
    const int b = blockIdx.x;
    const int tid = threadIdx.x;

    // zero the w output region (d_out is poisoned 0xAA)
    if (tid < VV) out_w[b * VV + tid] = 0.0f;

    xs[tid]       = x[b * CC + tid];
    xs[tid + 256] = x[b * CC + tid + 256];
    __syncthreads();

    const int wid = tid >> 5, lane = tid & 31;
    for (int j = wid; j < 3 * KK; j += 8) {
        const float* wr = W + j * CC;
        float s = 0.0f;
#pragma unroll
        for (int i = 0; i < CC; i += 32) s += wr[i + lane] * xs[i + lane];
#pragma unroll
        for (int o = 16; o; o >>= 1) s += __shfl_down_sync(0xffffffffu, s, o);
        if (lane == 0) {
            float p = __expf(s + bias[j]);
            if (j < KK) {
                g_alpha[b * KK + j] = p;
            } else if (j < 2 * KK) {
                g_beta[b * KK + (j - KK)] = p;
            } else {
                int k = j - 2 * KK;
                float kp = kap_old[b * KK + k] + p;
                g_kappa[b * KK + k] = kp;
                out_kappa[b * KK + k] = kp;
            }
        }
    }
}

// -------- Kernel 2: phi[b,t] = sum_k alpha * exp(-beta*(kappa-t)^2) --------
__global__ void k_phi(float* __restrict__ out_phi) {
    __shared__ float sa[KK], sb[KK], sk[KK];
    const int b = blockIdx.y;
    const int tid = threadIdx.x;
    if (tid < KK) {
        sa[tid] = g_alpha[b * KK + tid];
        sb[tid] = g_beta[b * KK + tid];
        sk[tid] = g_kappa[b * KK + tid];
    }
    __syncthreads();
    const int t = blockIdx.x * blockDim.x + tid;
    const float tf = (float)t;
    float s = 0.0f;
#pragma unroll
    for (int k = 0; k < KK; k++) {
        float d = sk[k] - tf;
        s += sa[k] * __expf(-sb[k] * d * d);
    }
    out_phi[b * TT + t] = s;
}

// -------- Kernel 3: w[b,v] += sum_t phi[b,t] * onehots[b,t,v] --------
// grid = (T/CHUNK, B), 256 threads. CHUNK = 128 rows of 128 floats.
// Thread layout: q = tid&31 -> float4 column index (32 * 4 = 128 v),
//                r = tid>>5 -> row group (8 rows in flight).
__global__ void k_w(const float* __restrict__ phi,
                    const float4* __restrict__ oh,
                    float* __restrict__ w) {
    __shared__ float s_phi[128];
    __shared__ float4 red[8][32];

    const int b = blockIdx.y;
    const int t0 = blockIdx.x * 128;
    const int tid = threadIdx.x;

    if (tid < 128) s_phi[tid] = phi[b * TT + t0 + tid];
    __syncthreads();

    const int q = tid & 31, r = tid >> 5;
    const float4* base = oh + (size_t)(b * TT + t0) * 32;  // 32 float4 per row

    float4 acc = make_float4(0.f, 0.f, 0.f, 0.f);
#pragma unroll
    for (int s = 0; s < 16; s++) {
        const int row = s * 8 + r;
        const float ph = s_phi[row];
        const float4 o = base[row * 32 + q];
        acc.x += ph * o.x;
        acc.y += ph * o.y;
        acc.z += ph * o.z;
        acc.w += ph * o.w;
    }
    red[r][q] = acc;
    __syncthreads();
    if (r < 4) {
        float4 o = red[r + 4][q];
        acc.x += o.x; acc.y += o.y; acc.z += o.z; acc.w += o.w;
        red[r][q] = acc;
    }
    __syncthreads();
    if (r < 2) {
        float4 o = red[r + 2][q];
        acc.x += o.x; acc.y += o.y; acc.z += o.z; acc.w += o.w;
        red[r][q] = acc;
    }
    __syncthreads();
    if (r == 0) {
        float4 o = red[1][q];
        acc.x += o.x; acc.y += o.y; acc.z += o.z; acc.w += o.w;
        float* dst = w + b * VV + q * 4;
        atomicAdd(dst + 0, acc.x);
        atomicAdd(dst + 1, acc.y);
        atomicAdd(dst + 2, acc.z);
        atomicAdd(dst + 3, acc.w);
    }
}

extern "C" void kernel_launch(void* const* d_in, const int* in_sizes, int n_in,
                              void* d_out, int out_size) {
    const float* x        = (const float*)d_in[0];  // (B, C)
    const float* kap_old  = (const float*)d_in[1];  // (B, K)
    const float* onehots  = (const float*)d_in[2];  // (B, T, V)
    const float* W        = (const float*)d_in[3];  // (3K, C)
    const float* bias     = (const float*)d_in[4];  // (3K,)

    float* out   = (float*)d_out;
    float* w_out = out;                       // (B, V)
    float* k_out = out + BB * VV;             // (B, K)
    float* p_out = out + BB * VV + BB * KK;   // (B, T)

    k_params<<<BB, 256>>>(x, kap_old, W, bias, w_out, k_out);
    k_phi<<<dim3(TT / 256, BB), 256>>>(p_out);
    k_w<<<dim3(TT / 128, BB), 256>>>(p_out, (const float4*)onehots, w_out);
}

// round 2
// speedup vs baseline: 1.1720x; 1.1720x over previous
#include <cuda_runtime.h>

#define BB 256
#define TT 2048
#define VV 128
#define CC 512
#define KK 10

// scratch (no device allocs allowed): [alpha | beta | kappa] per (b,k)
__device__ float g_alpha[BB * KK];
__device__ float g_beta[BB * KK];
__device__ float g_kappa[BB * KK];

// -------- Kernel 1: params GEMM, one warp per (b, j) --------
// 256 b * 30 j = 7680 warps -> 960 blocks of 8 warps.
// Also zeroes the w output region (atomics target) and writes kappa out.
__global__ void k_params(const float* __restrict__ x,
                         const float* __restrict__ kap_old,
                         const float* __restrict__ W,
                         const float* __restrict__ bias,
                         float* __restrict__ out_w,
                         float* __restrict__ out_kappa) {
    const int tid = threadIdx.x;
    const int gtid = blockIdx.x * blockDim.x + tid;

    // zero w output (poisoned 0xAA); 245760 threads >> 32768 elems
    if (gtid < BB * VV) out_w[gtid] = 0.0f;

    const int gw = gtid >> 5;           // global warp id
    if (gw >= BB * 3 * KK) return;
    const int lane = tid & 31;
    const int b = gw / (3 * KK);
    const int j = gw % (3 * KK);

    const float* xr = x + b * CC;
    const float* wr = W + j * CC;
    float s = 0.0f;
#pragma unroll
    for (int i = 0; i < CC; i += 32) s += wr[i + lane] * xr[i + lane];
#pragma unroll
    for (int o = 16; o; o >>= 1) s += __shfl_down_sync(0xffffffffu, s, o);

    if (lane == 0) {
        const float p = __expf(s + bias[j]);
        if (j < KK) {
            g_alpha[b * KK + j] = p;
        } else if (j < 2 * KK) {
            g_beta[b * KK + (j - KK)] = p;
        } else {
            const int k = j - 2 * KK;
            const float kp = kap_old[b * KK + k] + p;
            g_kappa[b * KK + k] = kp;
            out_kappa[b * KK + k] = kp;
        }
    }
}

// -------- Kernel 2 (fused phi + w reduce) --------
// grid = (T/128, B), 256 threads. Each block:
//   1. computes phi[b, t0:t0+128] from scratch params, writes p_out
//   2. streams 128 rows x 128 cols of onehots, accumulates phi-weighted sums
//   3. shared tree-reduce + atomicAdd into w
__global__ void k_w(const float4* __restrict__ oh,
                    float* __restrict__ p_out,
                    float* __restrict__ w) {
    __shared__ float sa[KK], sb[KK], sk[KK];
    __shared__ float s_phi[128];
    __shared__ float4 red[8][32];

    const int b = blockIdx.y;
    const int t0 = blockIdx.x * 128;
    const int tid = threadIdx.x;

    if (tid < KK) {
        sa[tid] = g_alpha[b * KK + tid];
        sb[tid] = g_beta[b * KK + tid];
        sk[tid] = g_kappa[b * KK + tid];
    }
    __syncthreads();

    if (tid < 128) {
        const float tf = (float)(t0 + tid);
        float s = 0.0f;
#pragma unroll
        for (int k = 0; k < KK; k++) {
            const float d = sk[k] - tf;
            s += sa[k] * __expf(-sb[k] * d * d);
        }
        s_phi[tid] = s;
        p_out[b * TT + t0 + tid] = s;
    }
    __syncthreads();

    const int q = tid & 31, r = tid >> 5;
    const float4* base = oh + (size_t)(b * TT + t0) * 32;  // 32 float4 per row

    float4 acc = make_float4(0.f, 0.f, 0.f, 0.f);
#pragma unroll
    for (int s = 0; s < 16; s++) {
        const int row = s * 8 + r;
        const float ph = s_phi[row];
        const float4 o = base[row * 32 + q];
        acc.x += ph * o.x;
        acc.y += ph * o.y;
        acc.z += ph * o.z;
        acc.w += ph * o.w;
    }
    red[r][q] = acc;
    __syncthreads();
    if (r < 4) {
        const float4 o = red[r + 4][q];
        acc.x += o.x; acc.y += o.y; acc.z += o.z; acc.w += o.w;
        red[r][q] = acc;
    }
    __syncthreads();
    if (r < 2) {
        const float4 o = red[r + 2][q];
        acc.x += o.x; acc.y += o.y; acc.z += o.z; acc.w += o.w;
        red[r][q] = acc;
    }
    __syncthreads();
    if (r == 0) {
        const float4 o = red[1][q];
        acc.x += o.x; acc.y += o.y; acc.z += o.z; acc.w += o.w;
        float* dst = w + b * VV + q * 4;
        atomicAdd(dst + 0, acc.x);
        atomicAdd(dst + 1, acc.y);
        atomicAdd(dst + 2, acc.z);
        atomicAdd(dst + 3, acc.w);
    }
}

extern "C" void kernel_launch(void* const* d_in, const int* in_sizes, int n_in,
                              void* d_out, int out_size) {
    const float* x        = (const float*)d_in[0];  // (B, C)
    const float* kap_old  = (const float*)d_in[1];  // (B, K)
    const float* onehots  = (const float*)d_in[2];  // (B, T, V)
    const float* W        = (const float*)d_in[3];  // (3K, C)
    const float* bias     = (const float*)d_in[4];  // (3K,)

    float* out   = (float*)d_out;
    float* w_out = out;                       // (B, V)
    float* k_out = out + BB * VV;             // (B, K)
    float* p_out = out + BB * VV + BB * KK;   // (B, T)

    k_params<<<(BB * 3 * KK) / 8, 256>>>(x, kap_old, W, bias, w_out, k_out);
    k_w<<<dim3(TT / 128, BB), 256>>>((const float4*)onehots, p_out, w_out);
}

// round 3
// speedup vs baseline: 1.1856x; 1.0116x over previous
#include <cuda_runtime.h>

#define BB 256
#define TT 2048
#define VV 128
#define CC 512
#define KK 10
#define CHUNK 256   // rows of onehots per block in k_w

// scratch (no device allocs allowed)
__device__ float g_alpha[BB * KK];
__device__ float g_beta[BB * KK];
__device__ float g_kappa[BB * KK];

// -------- Kernel 1: params GEMM, one warp per (b, j); also zeroes w --------
__global__ void k_params(const float* __restrict__ x,
                         const float* __restrict__ kap_old,
                         const float* __restrict__ W,
                         const float* __restrict__ bias,
                         float* __restrict__ out_w,
                         float* __restrict__ out_kappa) {
    const int tid = threadIdx.x;
    const int gtid = blockIdx.x * blockDim.x + tid;

    if (gtid < BB * VV) out_w[gtid] = 0.0f;   // d_out poisoned; atomics target

    const int gw = gtid >> 5;
    if (gw >= BB * 3 * KK) return;
    const int lane = tid & 31;
    const int b = gw / (3 * KK);
    const int j = gw % (3 * KK);

    const float4* xr = (const float4*)(x + b * CC);
    const float4* wr = (const float4*)(W + j * CC);
    float s = 0.0f;
#pragma unroll
    for (int i = 0; i < 4; i++) {
        const float4 a = xr[i * 32 + lane];
        const float4 v = wr[i * 32 + lane];
        s += a.x * v.x + a.y * v.y + a.z * v.z + a.w * v.w;
    }
#pragma unroll
    for (int o = 16; o; o >>= 1) s += __shfl_down_sync(0xffffffffu, s, o);

    if (lane == 0) {
        const float p = __expf(s + bias[j]);
        if (j < KK) {
            g_alpha[b * KK + j] = p;
        } else if (j < 2 * KK) {
            g_beta[b * KK + (j - KK)] = p;
        } else {
            const int k = j - 2 * KK;
            const float kp = kap_old[b * KK + k] + p;
            g_kappa[b * KK + k] = kp;
            out_kappa[b * KK + k] = kp;
        }
    }
}

// -------- Kernel 2 (fused phi + w reduce) --------
// grid = (T/CHUNK, B), 256 threads. Each block:
//   1. all 256 threads compute phi[b, t0 + tid], write p_out + shared
//   2. stream CHUNK rows x 128 cols of onehots (__ldcs, evict-first),
//      flat index i*256 + tid => fixed float4 column per thread
//   3. shared tree-reduce across 8 row groups + atomicAdd into w
__global__ void __launch_bounds__(256)
k_w(const float4* __restrict__ oh,
    float* __restrict__ p_out,
    float* __restrict__ w) {
    __shared__ float sa[KK], sb[KK], sk[KK];
    __shared__ float s_phi[CHUNK];
    __shared__ float4 red[8][32];

    const int b = blockIdx.y;
    const int t0 = blockIdx.x * CHUNK;
    const int tid = threadIdx.x;

    if (tid < KK) {
        sa[tid] = g_alpha[b * KK + tid];
        sb[tid] = g_beta[b * KK + tid];
        sk[tid] = g_kappa[b * KK + tid];
    }
    __syncthreads();

    {
        const float tf = (float)(t0 + tid);
        float s = 0.0f;
#pragma unroll
        for (int k = 0; k < KK; k++) {
            const float d = sk[k] - tf;
            s += sa[k] * __expf(-sb[k] * d * d);
        }
        s_phi[tid] = s;
        p_out[b * TT + t0 + tid] = s;
    }
    __syncthreads();

    const int q = tid & 31, r = tid >> 5;
    const float4* base = oh + (size_t)(b * TT + t0) * 32;  // 32 float4/row

    float4 acc = make_float4(0.f, 0.f, 0.f, 0.f);
#pragma unroll 8
    for (int i = 0; i < CHUNK / 8; i++) {
        const int idx = i * 256 + tid;           // row = i*8 + r, col = q
        const float4 o = __ldcs(base + idx);
        const float ph = s_phi[i * 8 + r];
        acc.x += ph * o.x;
        acc.y += ph * o.y;
        acc.z += ph * o.z;
        acc.w += ph * o.w;
    }

    red[r][q] = acc;
    __syncthreads();
    if (r < 4) {
        const float4 o = red[r + 4][q];
        acc.x += o.x; acc.y += o.y; acc.z += o.z; acc.w += o.w;
        red[r][q] = acc;
    }
    __syncthreads();
    if (r < 2) {
        const float4 o = red[r + 2][q];
        acc.x += o.x; acc.y += o.y; acc.z += o.z; acc.w += o.w;
        red[r][q] = acc;
    }
    __syncthreads();
    if (r == 0) {
        const float4 o = red[1][q];
        acc.x += o.x; acc.y += o.y; acc.z += o.z; acc.w += o.w;
        float* dst = w + b * VV + q * 4;
        atomicAdd(dst + 0, acc.x);
        atomicAdd(dst + 1, acc.y);
        atomicAdd(dst + 2, acc.z);
        atomicAdd(dst + 3, acc.w);
    }
}

extern "C" void kernel_launch(void* const* d_in, const int* in_sizes, int n_in,
                              void* d_out, int out_size) {
    const float* x        = (const float*)d_in[0];  // (B, C)
    const float* kap_old  = (const float*)d_in[1];  // (B, K)
    const float* onehots  = (const float*)d_in[2];  // (B, T, V)
    const float* W        = (const float*)d_in[3];  // (3K, C)
    const float* bias     = (const float*)d_in[4];  // (3K,)

    float* out   = (float*)d_out;
    float* w_out = out;                       // (B, V)
    float* k_out = out + BB * VV;             // (B, K)
    float* p_out = out + BB * VV + BB * KK;   // (B, T)

    k_params<<<(BB * 3 * KK) / 8, 256>>>(x, kap_old, W, bias, w_out, k_out);
    k_w<<<dim3(TT / CHUNK, BB), 256>>>((const float4*)onehots, p_out, w_out);
}